// round 3
// baseline (speedup 1.0000x reference)
#include <cuda_runtime.h>
#include <math.h>

#define B_TOTAL 65536
#define OBS 64
#define ACTD 16
#define IND 145
#define HID 256
#define FEAT 128
#define NENV 64
#define EMB 32
#define ROWS 64
#define NTHREADS 256

// ---- shared memory layout (float offsets) ----
#define SX_STRIDE 152
#define OFF_SX    0                       // 64*152 = 9728   (x input; later aliased by FEAT)
#define OFF_SA    9728                    // 64*256 = 16384  (h0; later W tile)
#define OFF_SB    (9728+16384)            // 64*256 = 16384  (h1; later f2e/best)
#define OFF_FEAT  0                       // 64*128 = 8192 (aliases SX, stride 128)
#define OFF_W     9728                    // 128*132 = 16896 (transposed W_proj tile)
#define WS_STRIDE 132
#define OFF_F2E   (9728+16896)            // 64*132 = 8448
#define F2E_STRIDE 132
#define OFF_BEST  (9728+16896+8448)       // 64*32 = 2048
#define OFF_DLOC  (OFF_BEST+2048)         // 64*4 = 256
#define OFF_EEMB  42496                   // 64*32 = 2048
#define OFF_COEF  (OFF_EEMB+2048)         // 64
#define OFF_MIND  (OFF_COEF+64)           // 64
#define OFF_MIDX  (OFF_MIND+64)           // 64 (ints)
#define OFF_WNL   (OFF_MIDX+64)           // 64 (ints)
#define SMEM_FLOATS (OFF_WNL+64)          // 44800 floats = 179200 bytes

// Dense layer: out[r][c] = leaky(sum_k in[r][k] * W[k*C+c] + b[c])
// thread layout: tx = tid%64 -> cols {tx + 64*j}, ty = tid/64 -> rows [ty*16, ty*16+16)
template<int NJ>
__device__ __forceinline__ void dense_layer(
    const float* __restrict__ in_s, int in_stride, int K,
    const float* __restrict__ W, const float* __restrict__ bias,
    float* __restrict__ out_s, int out_stride, int C, int tid)
{
    const int tx = tid & 63;
    const int ty = tid >> 6;
    float acc[16][NJ];
#pragma unroll
    for (int j = 0; j < NJ; j++) {
        float bb = __ldg(&bias[tx + 64 * j]);
#pragma unroll
        for (int rr = 0; rr < 16; rr++) acc[rr][j] = bb;
    }
    const float* ip = in_s + (ty * 16) * in_stride;
#pragma unroll 2
    for (int k = 0; k < K; k++) {
        float w[NJ];
#pragma unroll
        for (int j = 0; j < NJ; j++) w[j] = __ldg(&W[(size_t)k * C + tx + 64 * j]);
#pragma unroll
        for (int rr = 0; rr < 16; rr++) {
            float xv = ip[rr * in_stride + k];
#pragma unroll
            for (int j = 0; j < NJ; j++) acc[rr][j] = fmaf(xv, w[j], acc[rr][j]);
        }
    }
#pragma unroll
    for (int rr = 0; rr < 16; rr++) {
#pragma unroll
        for (int j = 0; j < NJ; j++) {
            float a = acc[rr][j];
            out_s[(ty * 16 + rr) * out_stride + tx + 64 * j] = fmaxf(a, 0.01f * a);
        }
    }
}

extern __shared__ float sm[];

__global__ void __launch_bounds__(NTHREADS, 1)
udp_encoder_kernel(
    const float* __restrict__ obs,  const float* __restrict__ act,
    const float* __restrict__ obs2, const float* __restrict__ rew,
    const float* __restrict__ W0,   const float* __restrict__ b0,
    const float* __restrict__ W1,   const float* __restrict__ b1,
    const float* __restrict__ W2,   const float* __restrict__ b2,
    const float* __restrict__ Wp,   const float* __restrict__ ee,
    const float* __restrict__ sig,  float* __restrict__ out)
{
    const int tid = threadIdx.x;
    const int blk = blockIdx.x;
    const size_t row0 = (size_t)blk * ROWS;

    // ---- load e_emb, sigma coefficients, init argmin state ----
    for (int i = tid; i < NENV * EMB; i += NTHREADS) sm[OFF_EEMB + i] = ee[i];
    if (tid < NENV) {
        float s = sig[tid];
        sm[OFF_COEF + tid] = -1.0f / (64.0f * s * s);   // exp(-sumsq/(64*s^2))
        sm[OFF_MIND + tid] = 3.0e38f;
        ((int*)sm)[OFF_MIDX + tid] = 0;
    }

    // ---- build input tile x = [obs, obs2-obs, act, rew]  (64 x 145) ----
    for (int i = tid; i < ROWS * OBS; i += NTHREADS) {
        int r = i >> 6, k = i & 63;
        float o  = obs [(row0 + r) * OBS + k];
        float o2 = obs2[(row0 + r) * OBS + k];
        sm[OFF_SX + r * SX_STRIDE + k]      = o;
        sm[OFF_SX + r * SX_STRIDE + 64 + k] = o2 - o;
    }
    for (int i = tid; i < ROWS * ACTD; i += NTHREADS) {
        int r = i >> 4, k = i & 15;
        sm[OFF_SX + r * SX_STRIDE + 128 + k] = act[(row0 + r) * ACTD + k];
    }
    if (tid < ROWS) sm[OFF_SX + tid * SX_STRIDE + 144] = rew[row0 + tid];
    __syncthreads();

    // ---- MLP ----
    dense_layer<4>(sm + OFF_SX, SX_STRIDE, IND, W0, b0, sm + OFF_SA, HID, HID, tid);
    __syncthreads();
    dense_layer<4>(sm + OFF_SA, HID, HID, W1, b1, sm + OFF_SB, HID, HID, tid);
    __syncthreads();
    dense_layer<2>(sm + OFF_SB, HID, HID, W2, b2, sm + OFF_FEAT, FEAT, FEAT, tid);
    __syncthreads();

    // ---- projection + distance + argmin, 4 envs per group ----
    const int cg = tid & 31;   // col group: 4 cols (one env, 4 emb dims)
    const int rg = tid >> 5;   // 8 row groups of 8 rows

    for (int g = 0; g < 16; g++) {
        // stage W_proj tile transposed: w_s[k][c], c = nl*32+e, stride 132
        for (int i = tid; i < 128 * 128; i += NTHREADS) {
            int c = i >> 7, k = i & 127;
            sm[OFF_W + k * WS_STRIDE + c] =
                Wp[((size_t)(g * 4 + (c >> 5)) * EMB + (c & 31)) * FEAT + k];
        }
        __syncthreads();

        float acc[8][4];
#pragma unroll
        for (int rr = 0; rr < 8; rr++)
#pragma unroll
            for (int j = 0; j < 4; j++) acc[rr][j] = 0.0f;

        const float* fp = sm + OFF_FEAT + (rg * 8) * FEAT;
#pragma unroll 2
        for (int k = 0; k < FEAT; k++) {
            float4 w = *(const float4*)(sm + OFF_W + k * WS_STRIDE + cg * 4);
#pragma unroll
            for (int rr = 0; rr < 8; rr++) {
                float xv = fp[rr * FEAT + k];
                acc[rr][0] = fmaf(xv, w.x, acc[rr][0]);
                acc[rr][1] = fmaf(xv, w.y, acc[rr][1]);
                acc[rr][2] = fmaf(xv, w.z, acc[rr][2]);
                acc[rr][3] = fmaf(xv, w.w, acc[rr][3]);
            }
        }
#pragma unroll
        for (int rr = 0; rr < 8; rr++) {
            int r = rg * 8 + rr;
            *(float4*)(sm + OFF_F2E + r * F2E_STRIDE + cg * 4) =
                make_float4(acc[rr][0], acc[rr][1], acc[rr][2], acc[rr][3]);
        }
        __syncthreads();

        // distances: thread -> (r = tid/4, nl = tid%4)
        {
            int r = tid >> 2, nl = tid & 3;
            const float* fv = sm + OFF_F2E + r * F2E_STRIDE + nl * 32;
            const float* ev = sm + OFF_EEMB + (g * 4 + nl) * 32;
            float ssum = 0.0f;
#pragma unroll
            for (int e = 0; e < 32; e++) { float d = fv[e] - ev[e]; ssum = fmaf(d, d, ssum); }
            int n = g * 4 + nl;
            float dist = expf(ssum * sm[OFF_COEF + n]);
            out[(size_t)B_TOTAL * 66 + (row0 + r) * 64 + n] = dist;  // distance output
            sm[OFF_DLOC + r * 4 + nl] = dist;
        }
        __syncthreads();

        // argmin update (strict <, ascending n = first-min semantics)
        if (tid < ROWS) {
            int r = tid;
            float mind = sm[OFF_MIND + r];
            int wn = -1;
#pragma unroll
            for (int nl = 0; nl < 4; nl++) {
                float d = sm[OFF_DLOC + r * 4 + nl];
                if (d < mind) { mind = d; wn = nl; }
            }
            sm[OFF_MIND + r] = mind;
            if (wn >= 0) ((int*)sm)[OFF_MIDX + r] = g * 4 + wn;
            ((int*)sm)[OFF_WNL + r] = wn;
        }
        __syncthreads();

        // copy winning embedding into best buffer
        {
            int r = tid >> 2, part = tid & 3;
            int wn = ((int*)sm)[OFF_WNL + r];
            if (wn >= 0) {
#pragma unroll
                for (int e = 0; e < 8; e++)
                    sm[OFF_BEST + r * 32 + part * 8 + e] =
                        sm[OFF_F2E + r * F2E_STRIDE + wn * 32 + part * 8 + e];
            }
        }
        __syncthreads();
    }

    // ---- final outputs ----
    const int* midx = (const int*)sm + OFF_MIDX;
    for (int i = tid; i < ROWS * EMB; i += NTHREADS) {
        int r = i >> 5, e = i & 31;
        size_t grow = row0 + r;
        out[grow * 32 + e] = sm[OFF_BEST + r * 32 + e];                           // chosen_embedding
        out[(size_t)B_TOTAL * 34 + grow * 32 + e] = sm[OFF_EEMB + midx[r] * 32 + e]; // chosen_mean
    }
    if (tid < ROWS) {
        size_t grow = row0 + tid;
        out[(size_t)B_TOTAL * 32 + grow] = sm[OFF_MIND + tid];   // chosen_dist
        out[(size_t)B_TOTAL * 33 + grow] = (float)midx[tid];     // idx
    }
}

extern "C" void kernel_launch(void* const* d_in, const int* in_sizes, int n_in,
                              void* d_out, int out_size) {
    const float* obs  = (const float*)d_in[0];
    const float* act  = (const float*)d_in[1];
    const float* obs2 = (const float*)d_in[2];
    const float* rew  = (const float*)d_in[3];
    const float* W0   = (const float*)d_in[4];
    const float* b0   = (const float*)d_in[5];
    const float* W1   = (const float*)d_in[6];
    const float* b1   = (const float*)d_in[7];
    const float* W2   = (const float*)d_in[8];
    const float* b2   = (const float*)d_in[9];
    const float* Wp   = (const float*)d_in[10];
    const float* ee   = (const float*)d_in[11];
    const float* sig  = (const float*)d_in[12];
    float* out = (float*)d_out;

    const size_t smem_bytes = (size_t)SMEM_FLOATS * sizeof(float); // 179200
    cudaFuncSetAttribute(udp_encoder_kernel,
                         cudaFuncAttributeMaxDynamicSharedMemorySize, (int)smem_bytes);

    dim3 grid(B_TOTAL / ROWS);   // 1024 blocks
    dim3 block(NTHREADS);
    udp_encoder_kernel<<<grid, block, smem_bytes>>>(
        obs, act, obs2, rew, W0, b0, W1, b1, W2, b2, Wp, ee, sig, out);
}

// round 10
// speedup vs baseline: 1.3959x; 1.3959x over previous
#include <cuda_runtime.h>
#include <math.h>

#define B_TOTAL 65536
#define OBS 64
#define ACTD 16
#define IND 145
#define HID 256
#define FEAT 128
#define NENV 64
#define EMB 32
#define ROWS 64
#define NTHREADS 512

typedef unsigned long long u64;

__device__ __forceinline__ u64 fma2(u64 a, u64 b, u64 c) {
    u64 d; asm("fma.rn.f32x2 %0,%1,%2,%3;" : "=l"(d) : "l"(a), "l"(b), "l"(c)); return d;
}
__device__ __forceinline__ u64 pack2(float x, float y) {
    u64 d; asm("mov.b64 %0,{%1,%2};" : "=l"(d) : "f"(x), "f"(y)); return d;
}
__device__ __forceinline__ void unpack2(u64 v, float& x, float& y) {
    asm("mov.b64 {%0,%1},%2;" : "=f"(x), "=f"(y) : "l"(v));
}

// ---- shared memory layout (float offsets) ----
// ALL region bases are multiples of 4 floats (16B) so float4 accesses are legal.
// transposed activation tiles: T[k][row], stride 66 (row pairs at even offsets -> 8B aligned v2)
#define TS 66
#define OFF_XT    0                        // 145*66 = 9570 -> pad to 9572
#define OFF_FEATT 0                        // FEATT (128*66=8448) aliases XT
#define OFF_H0T   9572                     // 256*66 = 16896 ; W_proj tile aliases here
#define OFF_WT    9572
#define WT_STRIDE 132
#define OFF_H1T   26468                    // 256*66 = 16896 ; f2e aliases here
#define OFF_F2E   26468
#define F2E_STRIDE 132
#define OFF_EEMB  43364                    // 64*32
#define OFF_BEST  45412                    // 64*32
#define OFF_COEF  47460                    // 64
#define OFF_MIND  47524                    // 64
#define OFF_MIDX  47588                    // 64 ints
#define OFF_WNL   47652                    // 64 ints
#define OFF_DLOC  47716                    // 256
#define SMEM_FLOATS 47972                  // 191888 bytes

// Transposed dense layer with packed f32x2 FMA.
// inT[k][row] (stride TS) -> outT[c][row] (stride TS)
// tx = tid&63 -> cols {tx+64j}, ty = tid>>6 -> rows [ty*8, ty*8+8) as 4 row-pairs
template<int NJ>
__device__ __forceinline__ void dense_layerT(
    const float* __restrict__ inT, int K,
    const float* __restrict__ W, const float* __restrict__ bias, int C,
    float* __restrict__ outT, int tid)
{
    const int tx = tid & 63;
    const int ty = tid >> 6;
    u64 acc[4][NJ];
#pragma unroll
    for (int j = 0; j < NJ; j++) {
        float bb = __ldg(&bias[tx + 64 * j]);
        u64 b2 = pack2(bb, bb);
#pragma unroll
        for (int p = 0; p < 4; p++) acc[p][j] = b2;
    }
    const float* ip = inT + ty * 8;
#pragma unroll 4
    for (int k = 0; k < K; k++) {
        u64 wv[NJ];
#pragma unroll
        for (int j = 0; j < NJ; j++) {
            float w = __ldg(&W[(size_t)k * C + tx + 64 * j]);
            wv[j] = pack2(w, w);
        }
        const float* col = ip + k * TS;
        u64 x0 = *(const u64*)(col + 0);
        u64 x1 = *(const u64*)(col + 2);
        u64 x2 = *(const u64*)(col + 4);
        u64 x3 = *(const u64*)(col + 6);
#pragma unroll
        for (int j = 0; j < NJ; j++) {
            acc[0][j] = fma2(x0, wv[j], acc[0][j]);
            acc[1][j] = fma2(x1, wv[j], acc[1][j]);
            acc[2][j] = fma2(x2, wv[j], acc[2][j]);
            acc[3][j] = fma2(x3, wv[j], acc[3][j]);
        }
    }
#pragma unroll
    for (int p = 0; p < 4; p++) {
#pragma unroll
        for (int j = 0; j < NJ; j++) {
            float a, b; unpack2(acc[p][j], a, b);
            int c = tx + 64 * j;
            outT[c * TS + ty * 8 + 2 * p]     = fmaxf(a, 0.01f * a);
            outT[c * TS + ty * 8 + 2 * p + 1] = fmaxf(b, 0.01f * b);
        }
    }
}

extern __shared__ float sm[];

__global__ void __launch_bounds__(NTHREADS, 1)
udp_encoder_kernel(
    const float* __restrict__ obs,  const float* __restrict__ act,
    const float* __restrict__ obs2, const float* __restrict__ rew,
    const float* __restrict__ W0,   const float* __restrict__ b0,
    const float* __restrict__ W1,   const float* __restrict__ b1,
    const float* __restrict__ W2,   const float* __restrict__ b2,
    const float* __restrict__ Wp,   const float* __restrict__ ee,
    const float* __restrict__ sig,  float* __restrict__ out)
{
    const int tid = threadIdx.x;
    const size_t row0 = (size_t)blockIdx.x * ROWS;

    // ---- e_emb, sigma coefficients, argmin init ----
    for (int i = tid; i < NENV * EMB; i += NTHREADS) sm[OFF_EEMB + i] = ee[i];
    if (tid < NENV) {
        float s = sig[tid];
        sm[OFF_COEF + tid] = -1.0f / (64.0f * s * s);
        sm[OFF_MIND + tid] = 3.0e38f;
        ((int*)sm)[OFF_MIDX + tid] = 0;
    }

    // ---- build transposed input tile xT[k][row], k in [0,145) ----
    for (int i = tid; i < ROWS * OBS; i += NTHREADS) {
        int r = i >> 6, k = i & 63;
        float o  = obs [(row0 + r) * OBS + k];
        float o2 = obs2[(row0 + r) * OBS + k];
        sm[OFF_XT + k * TS + r]        = o;
        sm[OFF_XT + (64 + k) * TS + r] = o2 - o;
    }
    for (int i = tid; i < ROWS * ACTD; i += NTHREADS) {
        int r = i >> 4, k = i & 15;
        sm[OFF_XT + (128 + k) * TS + r] = act[(row0 + r) * ACTD + k];
    }
    if (tid < ROWS) sm[OFF_XT + 144 * TS + tid] = rew[row0 + tid];
    __syncthreads();

    // ---- MLP (all transposed, f32x2) ----
    dense_layerT<4>(sm + OFF_XT,  IND, W0, b0, HID,  sm + OFF_H0T,   tid);
    __syncthreads();
    dense_layerT<4>(sm + OFF_H0T, HID, W1, b1, HID,  sm + OFF_H1T,   tid);
    __syncthreads();
    dense_layerT<2>(sm + OFF_H1T, HID, W2, b2, FEAT, sm + OFF_FEATT, tid);
    __syncthreads();

    // ---- projection + distance + argmin, 4 envs per group ----
    const int cg = tid & 31;   // 4 cols (one env, 4 emb dims)
    const int rg = tid >> 5;   // 16 row groups of 4 rows (2 pairs)

    for (int g = 0; g < 16; g++) {
        // stage W_proj tile transposed: wt[k][c], c = env_local*32 + e
        for (int i = tid; i < 128 * 128; i += NTHREADS) {
            int c = i >> 7, k = i & 127;
            sm[OFF_WT + k * WT_STRIDE + c] =
                Wp[((size_t)(g * 4 + (c >> 5)) * EMB + (c & 31)) * FEAT + k];
        }
        __syncthreads();

        u64 acc[2][4];
#pragma unroll
        for (int p = 0; p < 2; p++)
#pragma unroll
            for (int j = 0; j < 4; j++) acc[p][j] = 0ULL;

        const float* fp = sm + OFF_FEATT + rg * 4;
        const float* wp = sm + OFF_WT + cg * 4;
#pragma unroll 4
        for (int k = 0; k < FEAT; k++) {
            float4 w = *(const float4*)(wp + k * WT_STRIDE);
            u64 w0 = pack2(w.x, w.x), w1 = pack2(w.y, w.y);
            u64 w2v = pack2(w.z, w.z), w3 = pack2(w.w, w.w);
            u64 x0 = *(const u64*)(fp + k * TS);
            u64 x1 = *(const u64*)(fp + k * TS + 2);
            acc[0][0] = fma2(x0, w0, acc[0][0]);
            acc[0][1] = fma2(x0, w1, acc[0][1]);
            acc[0][2] = fma2(x0, w2v, acc[0][2]);
            acc[0][3] = fma2(x0, w3, acc[0][3]);
            acc[1][0] = fma2(x1, w0, acc[1][0]);
            acc[1][1] = fma2(x1, w1, acc[1][1]);
            acc[1][2] = fma2(x1, w2v, acc[1][2]);
            acc[1][3] = fma2(x1, w3, acc[1][3]);
        }
        // store f2e rows (row-major, stride 132), float4 stores (16B-aligned base)
#pragma unroll
        for (int p = 0; p < 2; p++) {
            float a0, b0v, a1, b1v, a2, b2v, a3, b3v;
            unpack2(acc[p][0], a0, b0v);
            unpack2(acc[p][1], a1, b1v);
            unpack2(acc[p][2], a2, b2v);
            unpack2(acc[p][3], a3, b3v);
            int r = rg * 4 + 2 * p;
            *(float4*)(sm + OFF_F2E + r * F2E_STRIDE + cg * 4) =
                make_float4(a0, a1, a2, a3);
            *(float4*)(sm + OFF_F2E + (r + 1) * F2E_STRIDE + cg * 4) =
                make_float4(b0v, b1v, b2v, b3v);
        }
        __syncthreads();

        // distances: threads 0..255 -> (r = tid/4, nl = tid%4)
        if (tid < 256) {
            int r = tid >> 2, nl = tid & 3;
            const float* fv = sm + OFF_F2E + r * F2E_STRIDE + nl * 32;
            const float* ev = sm + OFF_EEMB + (g * 4 + nl) * 32;
            float ssum = 0.0f;
#pragma unroll
            for (int e = 0; e < 32; e++) { float d = fv[e] - ev[e]; ssum = fmaf(d, d, ssum); }
            int n = g * 4 + nl;
            float dist = expf(ssum * sm[OFF_COEF + n]);
            out[(size_t)B_TOTAL * 66 + (row0 + r) * 64 + n] = dist;
            sm[OFF_DLOC + r * 4 + nl] = dist;
        }
        __syncthreads();

        // argmin update (strict <, ascending order = first-min semantics)
        if (tid < ROWS) {
            int r = tid;
            float mind = sm[OFF_MIND + r];
            int wn = -1;
#pragma unroll
            for (int nl = 0; nl < 4; nl++) {
                float d = sm[OFF_DLOC + r * 4 + nl];
                if (d < mind) { mind = d; wn = nl; }
            }
            sm[OFF_MIND + r] = mind;
            if (wn >= 0) ((int*)sm)[OFF_MIDX + r] = g * 4 + wn;
            ((int*)sm)[OFF_WNL + r] = wn;
        }
        __syncthreads();

        // copy winning embedding into best buffer
        if (tid < 256) {
            int r = tid >> 2, part = tid & 3;
            int wn = ((int*)sm)[OFF_WNL + r];
            if (wn >= 0) {
#pragma unroll
                for (int e = 0; e < 8; e++)
                    sm[OFF_BEST + r * 32 + part * 8 + e] =
                        sm[OFF_F2E + r * F2E_STRIDE + wn * 32 + part * 8 + e];
            }
        }
        __syncthreads();
    }

    // ---- final outputs ----
    const int* midx = (const int*)sm + OFF_MIDX;
    for (int i = tid; i < ROWS * EMB; i += NTHREADS) {
        int r = i >> 5, e = i & 31;
        size_t grow = row0 + r;
        out[grow * 32 + e] = sm[OFF_BEST + r * 32 + e];                              // chosen_embedding
        out[(size_t)B_TOTAL * 34 + grow * 32 + e] = sm[OFF_EEMB + midx[r] * 32 + e]; // chosen_mean
    }
    if (tid < ROWS) {
        size_t grow = row0 + tid;
        out[(size_t)B_TOTAL * 32 + grow] = sm[OFF_MIND + tid];   // chosen_dist
        out[(size_t)B_TOTAL * 33 + grow] = (float)midx[tid];     // idx
    }
}

extern "C" void kernel_launch(void* const* d_in, const int* in_sizes, int n_in,
                              void* d_out, int out_size) {
    const float* obs  = (const float*)d_in[0];
    const float* act  = (const float*)d_in[1];
    const float* obs2 = (const float*)d_in[2];
    const float* rew  = (const float*)d_in[3];
    const float* W0   = (const float*)d_in[4];
    const float* b0   = (const float*)d_in[5];
    const float* W1   = (const float*)d_in[6];
    const float* b1   = (const float*)d_in[7];
    const float* W2   = (const float*)d_in[8];
    const float* b2   = (const float*)d_in[9];
    const float* Wp   = (const float*)d_in[10];
    const float* ee   = (const float*)d_in[11];
    const float* sig  = (const float*)d_in[12];
    float* out = (float*)d_out;

    const size_t smem_bytes = (size_t)SMEM_FLOATS * sizeof(float); // 191888
    cudaFuncSetAttribute(udp_encoder_kernel,
                         cudaFuncAttributeMaxDynamicSharedMemorySize, (int)smem_bytes);

    dim3 grid(B_TOTAL / ROWS);   // 1024 blocks
    dim3 block(NTHREADS);
    udp_encoder_kernel<<<grid, block, smem_bytes>>>(
        obs, act, obs2, rew, W0, b0, W1, b1, W2, b2, Wp, ee, sig, out);
}